// round 14
// baseline (speedup 1.0000x reference)
#include <cuda_runtime.h>
#include <cstdint>

#define NN 50000
#define EE 400000
#define MM 800000
#define HH 128
#define HM 256
#define BN_EPS 1e-5f

// ---------------- device scratch ----------------
__device__ float g_lift[(size_t)EE * HH];
__device__ float g_y1  [(size_t)EE * HH];
__device__ float g_lvl [(size_t)NN * HH];
__device__ float g_yb1 [(size_t)NN * HM];
__device__ float g_yl1 [(size_t)EE * HM];
__device__ float g_wt  [196608];             // fragment-order tf32 weights
__device__ float g_sum  [5 * 256];
__device__ float g_sumsq[5 * 256];
__device__ float g_scale[5 * 256];
__device__ float g_shift[5 * 256];

// weight offsets inside g_wt
#define WT_M  0        // merged [K=256, NC=384]  (Wa | [Wl1; (1+eps2)Wl1])
#define WT_B1 98304    // Wb1 [128,256]
#define WT_B2 131072   // Wb2 [256,128]
#define WT_L2 163840   // Wl2 [256,128]

// ---------------- helpers ----------------
__device__ __forceinline__ float f2tf(float x) {
    uint32_t r;
    asm("cvt.rna.tf32.f32 %0, %1;" : "=r"(r) : "f"(x));
    return __uint_as_float(r);
}
__device__ __forceinline__ uint32_t smem_u32(const void* p) {
    uint32_t a;
    asm("{ .reg .u64 t; cvta.to.shared.u64 t, %1; cvt.u32.u64 %0, t; }" : "=r"(a) : "l"(p));
    return a;
}
__device__ __forceinline__ void cp_async16(uint32_t d, const void* s) {
    asm volatile("cp.async.ca.shared.global [%0], [%1], 16;" :: "r"(d), "l"(s) : "memory");
}
__device__ __forceinline__ void cp_commit() {
    asm volatile("cp.async.commit_group;" ::: "memory");
}
__device__ __forceinline__ void cp_wait_all() {
    asm volatile("cp.async.wait_group 0;" ::: "memory");
}
__device__ __forceinline__ void mma_tf32(float* c, const uint32_t* a, const uint32_t* b) {
    asm volatile("mma.sync.aligned.m16n8k8.row.col.f32.tf32.tf32.f32 "
                 "{%0,%1,%2,%3}, {%4,%5,%6,%7}, {%8,%9}, {%0,%1,%2,%3};"
                 : "+f"(c[0]), "+f"(c[1]), "+f"(c[2]), "+f"(c[3])
                 : "r"(a[0]), "r"(a[1]), "r"(a[2]), "r"(a[3]),
                   "r"(b[0]), "r"(b[1]));
}
__device__ __forceinline__ void red_add_v4(float* p, float4 v) {
    asm volatile("red.global.add.v4.f32 [%0], {%1,%2,%3,%4};"
                 :: "l"(p), "f"(v.x), "f"(v.y), "f"(v.z), "f"(v.w) : "memory");
}

// ---------------- prep: zero scratch + build fragment-order tf32 weights ----------------
// fragment layout per weight (K x NC): dst = ch*NC*32 + (n>>3)*256 + (klc>>3)*64
//                                          + (n&7)*8 + (klc&3)*2 + ((klc>>2)&1)
__global__ void k_prep(const float* __restrict__ Wa,  const float* __restrict__ Wb1,
                       const float* __restrict__ Wb2, const float* __restrict__ Wl1,
                       const float* __restrict__ Wl2, const float* __restrict__ eps2p,
                       float* __restrict__ wfrag,
                       float* __restrict__ lift, float* __restrict__ lvl,
                       float* __restrict__ sums)
{
    long long t = (long long)blockIdx.x * blockDim.x + threadIdx.x;
    const long long stride = (long long)gridDim.x * blockDim.x;
    const long long n1 = (long long)EE * HH / 4;
    for (long long i = t; i < n1; i += stride)
        ((float4*)lift)[i] = make_float4(0.f, 0.f, 0.f, 0.f);
    const long long n2 = (long long)NN * HH / 4;
    for (long long i = t; i < n2; i += stride)
        ((float4*)lvl)[i] = make_float4(0.f, 0.f, 0.f, 0.f);
    if (t < 2560) sums[t] = 0.f;
    const float e2 = 1.0f + *eps2p;
    for (long long i = t; i < 196608; i += stride) {
        float val; int K, NC, k, n, base;
        if (i < 98304) {
            // merged weight: K=256, NC=384
            K = 256; NC = 384; base = WT_M;
            int e = (int)i;
            k = e / 384; n = e % 384;
            if (n < 128)      val = Wa[(size_t)k * 128 + n];
            else if (k < 128) val = Wl1[(size_t)k * 256 + (n - 128)];
            else              val = e2 * Wl1[(size_t)(k - 128) * 256 + (n - 128)];
        } else {
            int e2i = (int)(i - 98304);
            int w = e2i >> 15;           // 0:Wb1 1:Wb2 2:Wl2
            int e = e2i & 32767;
            K  = (w == 0) ? 128 : 256;
            NC = 32768 / K;
            base = 98304 + w * 32768;
            k = e / NC; n = e % NC;
            const float* W = (w == 0) ? Wb1 : (w == 1) ? Wb2 : Wl2;
            val = W[(size_t)k * NC + n];
        }
        int ch = k >> 5, klc = k & 31;
        int dst = base + ch * NC * 32 + (n >> 3) * 256 + (klc >> 3) * 64 +
                  (n & 7) * 8 + (klc & 3) * 2 + ((klc >> 2) & 1);
        wfrag[dst] = f2tf(val);
    }
}

// ---------------- scatter: out[sidx[m]] += vals[gidx[m]] (rows of 128) ----------------
__global__ void k_scatter(const float* __restrict__ vals,
                          const int*   __restrict__ gidx,
                          const int*   __restrict__ sidx,
                          float*       __restrict__ out)
{
    int t = blockIdx.x * blockDim.x + threadIdx.x;
    int m = t >> 5;
    if (m >= MM) return;
    int lane = t & 31;
    int g = __ldg(gidx + m);
    int s = __ldg(sidx + m);
    float4 v = *(const float4*)(vals + (size_t)g * HH + lane * 4);
    red_add_v4(out + (size_t)s * HH + lane * 4, v);
}

// ---------------- scatter with fused BN-ReLU on the gathered rows ----------------
__global__ void k_scatter_bn(const float* __restrict__ vals,
                             const int*   __restrict__ gidx,
                             const int*   __restrict__ sidx,
                             const float* __restrict__ scale,
                             const float* __restrict__ shift,
                             float*       __restrict__ out)
{
    int t = blockIdx.x * blockDim.x + threadIdx.x;
    int m = t >> 5;
    if (m >= MM) return;
    int lane = t & 31;
    int g = __ldg(gidx + m);
    int s = __ldg(sidx + m);
    float4 v  = *(const float4*)(vals + (size_t)g * HH + lane * 4);
    float4 sc = *(const float4*)(scale + lane * 4);
    float4 sh = *(const float4*)(shift + lane * 4);
    v.x = fmaxf(fmaf(v.x, sc.x, sh.x), 0.f);
    v.y = fmaxf(fmaf(v.y, sc.y, sh.y), 0.f);
    v.z = fmaxf(fmaf(v.z, sc.z, sh.z), 0.f);
    v.w = fmaxf(fmaf(v.w, sc.w, sh.w), 0.f);
    red_add_v4(out + (size_t)s * HH + lane * 4, v);
}

// ---------------- GEMM mainloop body ----------------
// B addressing uses (NcolsB, c0B); C/stats use (C, Cstride, c0C, osum[c0C+col]).
template <int MODE, int K>
__device__ __forceinline__ void gemm_body(
    const float* __restrict__ A0, const float* __restrict__ A1,
    const float* __restrict__ scl, const float* __restrict__ shf,
    float et,
    const float* __restrict__ Bt, int NcolsB, int c0B,
    float* __restrict__ C, int Cstride, int c0C, int Rows,
    float* __restrict__ osum, float* __restrict__ osumsq,
    int bx, float* __restrict__ smem, uint32_t sB_u32)
{
    float* __restrict__ sA = smem;          // [2][4096]
    float* __restrict__ sB = smem + 8192;   // [2][4096]

    constexpr int NCH = K / 32;

    int tid = threadIdx.x;
    int lane = tid & 31, wid = tid >> 5;
    int wm = wid >> 1, wn = wid & 1;
    int r0 = bx * 128;

    float4 areg[4];

    auto loadA = [&](int ch) {
        int kt = ch * 32;
#pragma unroll
        for (int i = 0; i < 4; i++) {
            int idx = i * 256 + tid;
            int row = idx >> 3, q = idx & 7;
            int gr = r0 + row, k = kt + q * 4;
            float4 v = make_float4(0.f, 0.f, 0.f, 0.f);
            if (gr < Rows) {
                if (MODE == 1) {
                    const float* s = (k < 128) ? A0 + (size_t)gr * 128 + k
                                               : A1 + (size_t)gr * 128 + (k - 128);
                    v = *(const float4*)s;
                } else if (MODE == 2) {
                    float4 x = *(const float4*)(A0 + (size_t)gr * 128 + k);
                    float4 y = *(const float4*)(A1 + (size_t)gr * 128 + k);
                    v.x = fmaf(et, x.x, y.x); v.y = fmaf(et, x.y, y.y);
                    v.z = fmaf(et, x.z, y.z); v.w = fmaf(et, x.w, y.w);
                } else {
                    float4 r4 = *(const float4*)(A0 + (size_t)gr * K + k);
                    float4 s4 = *(const float4*)(scl + k);
                    float4 h4 = *(const float4*)(shf + k);
                    v.x = fmaxf(fmaf(r4.x, s4.x, h4.x), 0.f);
                    v.y = fmaxf(fmaf(r4.y, s4.y, h4.y), 0.f);
                    v.z = fmaxf(fmaf(r4.z, s4.z, h4.z), 0.f);
                    v.w = fmaxf(fmaf(r4.w, s4.w, h4.w), 0.f);
                }
            }
            areg[i] = v;
        }
    };
    auto stsA = [&](int buf) {
        float* __restrict__ d = sA + buf * 4096;
#pragma unroll
        for (int i = 0; i < 4; i++) {
            int idx = i * 256 + tid;
            int row = idx >> 3, q = idx & 7;
            int mt = row >> 4, ks = q >> 1;
            int r = ((row >> 3) & 1) + 2 * (q & 1);
            int base = ((mt * 4 + ks) * 32 + (row & 7) * 4) * 4 + r;
            d[base + 0 ] = f2tf(areg[i].x);
            d[base + 4 ] = f2tf(areg[i].y);
            d[base + 8 ] = f2tf(areg[i].z);
            d[base + 12] = f2tf(areg[i].w);
        }
    };
    auto cpB = [&](int ch, int buf) {
        const float* __restrict__ src = Bt + (size_t)ch * (NcolsB * 32) + c0B * 32;
        uint32_t dst = sB_u32 + buf * 16384;
#pragma unroll
        for (int i = 0; i < 4; i++) {
            int idx = i * 256 + tid;
            cp_async16(dst + idx * 16, src + idx * 4);
        }
        cp_commit();
    };

    float acc[2][8][4];
#pragma unroll
    for (int mt = 0; mt < 2; mt++)
#pragma unroll
        for (int nt = 0; nt < 8; nt++)
#pragma unroll
            for (int r = 0; r < 4; r++) acc[mt][nt][r] = 0.f;

    cpB(0, 0);
    loadA(0);
    stsA(0);
    cp_wait_all();
    __syncthreads();

    for (int ch = 0; ch < NCH; ch++) {
        int buf = ch & 1;
        if (ch + 1 < NCH) { cpB(ch + 1, buf ^ 1); loadA(ch + 1); }
        const float* __restrict__ pa = sA + buf * 4096;
        const float* __restrict__ pb = sB + buf * 4096;
#pragma unroll
        for (int ks = 0; ks < 4; ks++) {
            uint4 av[2];
            uint2 bv[8];
#pragma unroll
            for (int mt = 0; mt < 2; mt++)
                av[mt] = *(const uint4*)(pa + (((wm * 2 + mt) * 4 + ks) * 32 + lane) * 4);
#pragma unroll
            for (int nt = 0; nt < 8; nt++)
                bv[nt] = *(const uint2*)(pb + (((wn * 8 + nt) * 4 + ks) * 32 + lane) * 2);
#pragma unroll
            for (int mt = 0; mt < 2; mt++)
#pragma unroll
                for (int nt = 0; nt < 8; nt++)
                    mma_tf32(acc[mt][nt], (const uint32_t*)&av[mt], (const uint32_t*)&bv[nt]);
        }
        if (ch + 1 < NCH) stsA(buf ^ 1);
        cp_wait_all();
        __syncthreads();
    }

    // ---- epilogue: store C + fused column stats ----
    int g = lane >> 2, t = lane & 3;
#pragma unroll
    for (int mt = 0; mt < 2; mt++) {
        int ra = r0 + wm * 32 + mt * 16 + g;
        int rb = ra + 8;
#pragma unroll
        for (int nt = 0; nt < 8; nt++) {
            int col = c0C + wn * 64 + nt * 8 + 2 * t;
            if (ra < Rows) {
                float2 v = make_float2(acc[mt][nt][0], acc[mt][nt][1]);
                *(float2*)(C + (size_t)ra * Cstride + col) = v;
            }
            if (rb < Rows) {
                float2 v = make_float2(acc[mt][nt][2], acc[mt][nt][3]);
                *(float2*)(C + (size_t)rb * Cstride + col) = v;
            }
        }
    }
#pragma unroll
    for (int nt = 0; nt < 8; nt++) {
#pragma unroll
        for (int p = 0; p < 2; p++) {
            float a0 = acc[0][nt][p],     a1 = acc[0][nt][p + 2];
            float a2 = acc[1][nt][p],     a3 = acc[1][nt][p + 2];
            float s  = a0 + a1 + a2 + a3;
            float ss = a0 * a0 + a1 * a1 + a2 * a2 + a3 * a3;
#pragma unroll
            for (int off = 4; off < 32; off <<= 1) {
                s  += __shfl_xor_sync(0xFFFFFFFFu, s,  off);
                ss += __shfl_xor_sync(0xFFFFFFFFu, ss, off);
            }
            if (g == 0) {
                int col = c0C + wn * 64 + nt * 8 + 2 * t + p;
                atomicAdd(osum + col, s);
                atomicAdd(osumsq + col, ss);
            }
        }
    }
}

// ---------------- merged GEMM: concat(lift,edge)[E,256] @ W'[256,384] ----------------
// blockIdx.y==0 -> y1 (stride 128, stats slot0); y==1,2 -> yl1 (stride 256, stats slot768)
__global__ __launch_bounds__(256, 2)
void k_gemm_merged(const float* __restrict__ lift, const float* __restrict__ edge,
                   const float* __restrict__ Bt,
                   float* __restrict__ y1, float* __restrict__ yl1,
                   float* __restrict__ sum0, float* __restrict__ sumsq0,
                   float* __restrict__ suml, float* __restrict__ sumsql)
{
    extern __shared__ float smem[];
    uint32_t sB_u32 = smem_u32(smem + 8192);
    int by = blockIdx.y;
    int c0B = by * 128;
    if (by == 0) {
        gemm_body<1, 256>(lift, edge, nullptr, nullptr, 1.0f,
                          Bt, 384, c0B, y1, 128, 0, EE,
                          sum0, sumsq0, blockIdx.x, smem, sB_u32);
    } else {
        gemm_body<1, 256>(lift, edge, nullptr, nullptr, 1.0f,
                          Bt, 384, c0B, yl1, 256, (by - 1) * 128, EE,
                          suml, sumsql, blockIdx.x, smem, sB_u32);
    }
}

// ---------------- single-problem GEMM ----------------
template <int MODE, int K>
__global__ __launch_bounds__(256, 2)
void k_gemm_mma(const float* __restrict__ A0, const float* __restrict__ A1,
                const float* __restrict__ scl, const float* __restrict__ shf,
                const float* __restrict__ epsp,
                const float* __restrict__ Bt,
                float* __restrict__ C, int Rows, int Ncols,
                float* __restrict__ osum, float* __restrict__ osumsq)
{
    extern __shared__ float smem[];
    uint32_t sB_u32 = smem_u32(smem + 8192);
    float et = 1.0f;
    if (MODE == 2) et = 1.0f + *epsp;
    int c0 = blockIdx.y * 128;
    gemm_body<MODE, K>(A0, A1, scl, shf, et, Bt, Ncols, c0, C, Ncols, c0, Rows,
                       osum, osumsq, blockIdx.x, smem, sB_u32);
}

// ---------------- two same-shape problems in one grid (restrict-selected) ----------------
template <int MODE, int K>
__global__ __launch_bounds__(256, 2)
void k_gemm_pair(const float* A0a, const float* A1a, const float* scla, const float* shfa,
                 const float* epsa, const float* Bta, float* Ca, int Rowsa,
                 float* osuma, float* osumsqa,
                 const float* A0b, const float* A1b, const float* sclb, const float* shfb,
                 const float* epsb, const float* Btb, float* Cb, int Rowsb,
                 float* osumb, float* osumsqb,
                 int gxa, int Ncols)
{
    extern __shared__ float smem[];
    uint32_t sB_u32 = smem_u32(smem + 8192);

    const bool isB = (int)blockIdx.x >= gxa;
    const float* __restrict__ A0  = isB ? A0b  : A0a;
    const float* __restrict__ A1  = isB ? A1b  : A1a;
    const float* __restrict__ scl = isB ? sclb : scla;
    const float* __restrict__ shf = isB ? shfb : shfa;
    const float* __restrict__ Bt  = isB ? Btb  : Bta;
    float* __restrict__ C         = isB ? Cb   : Ca;
    float* __restrict__ osum      = isB ? osumb : osuma;
    float* __restrict__ osumsq    = isB ? osumsqb : osumsqa;
    int Rows = isB ? Rowsb : Rowsa;
    int bx   = isB ? (int)blockIdx.x - gxa : (int)blockIdx.x;

    float et = 1.0f;
    if (MODE == 2) et = 1.0f + *(isB ? epsb : epsa);

    int c0 = blockIdx.y * 128;
    gemm_body<MODE, K>(A0, A1, scl, shf, et, Bt, Ncols, c0, C, Ncols, c0, Rows,
                       osum, osumsq, bx, smem, sB_u32);
}

// ---------------- BN scale/shift from sums (single) ----------------
__global__ void k_finalize(int C, float invR,
                           const float* __restrict__ g, const float* __restrict__ b,
                           const float* __restrict__ sum, const float* __restrict__ sumsq,
                           float* __restrict__ scale, float* __restrict__ shift)
{
    int c = threadIdx.x;
    if (c < C) {
        float m   = sum[c] * invR;
        float var = sumsq[c] * invR - m * m;
        float s   = g[c] * rsqrtf(var + BN_EPS);
        scale[c] = s;
        shift[c] = b[c] - m * s;
    }
}

// ---------------- BN scale/shift for two norms in one launch (512 threads) ----------------
__global__ void k_finalize2(int C1, float invR1, const float* __restrict__ g1,
                            const float* __restrict__ b1, const float* __restrict__ sum1,
                            const float* __restrict__ sumsq1, float* __restrict__ scale1,
                            float* __restrict__ shift1,
                            int C2, float invR2, const float* __restrict__ g2,
                            const float* __restrict__ b2, const float* __restrict__ sum2,
                            const float* __restrict__ sumsq2, float* __restrict__ scale2,
                            float* __restrict__ shift2)
{
    int t = threadIdx.x;
    if (t < 256) {
        if (t < C1) {
            float m   = sum1[t] * invR1;
            float var = sumsq1[t] * invR1 - m * m;
            float s   = g1[t] * rsqrtf(var + BN_EPS);
            scale1[t] = s;
            shift1[t] = b1[t] - m * s;
        }
    } else {
        int c = t - 256;
        if (c < C2) {
            float m   = sum2[c] * invR2;
            float var = sumsq2[c] * invR2 - m * m;
            float s   = g2[c] * rsqrtf(var + BN_EPS);
            scale2[c] = s;
            shift2[c] = b2[c] - m * s;
        }
    }
}

// ---------------- in-place BN affine + ReLU for two tensors ----------------
__global__ void k_apply2(float* __restrict__ X1, long long n4_1,
                         const float* __restrict__ scale1, const float* __restrict__ shift1,
                         float* __restrict__ X2, long long n4_2,
                         const float* __restrict__ scale2, const float* __restrict__ shift2)
{
    long long total = n4_1 + n4_2;
    for (long long idx = blockIdx.x * (long long)blockDim.x + threadIdx.x; idx < total;
         idx += (long long)gridDim.x * blockDim.x) {
        float* X; const float *scale, *shift; long long i;
        if (idx < n4_1) { X = X1; scale = scale1; shift = shift1; i = idx; }
        else            { X = X2; scale = scale2; shift = shift2; i = idx - n4_1; }
        int c4 = (int)(i & 31);
        float4 v  = ((float4*)X)[i];
        float4 sc = *(const float4*)(scale + c4 * 4);
        float4 sh = *(const float4*)(shift + c4 * 4);
        v.x = fmaxf(fmaf(v.x, sc.x, sh.x), 0.f);
        v.y = fmaxf(fmaf(v.y, sc.y, sh.y), 0.f);
        v.z = fmaxf(fmaf(v.z, sc.z, sh.z), 0.f);
        v.w = fmaxf(fmaf(v.w, sc.w, sh.w), 0.f);
        ((float4*)X)[i] = v;
    }
}

// ---------------- launch ----------------
extern "C" void kernel_launch(void* const* d_in, const int* in_sizes, int n_in,
                              void* d_out, int out_size)
{
    const float* node_rep = (const float*)d_in[0];
    const float* edge_rep = (const float*)d_in[1];
    const int*   n2e      = (const int*)  d_in[2];
    const int*   src = n2e;
    const int*   dst = n2e + MM;
    const float* Wa  = (const float*)d_in[3];
    const float* ga  = (const float*)d_in[4];
    const float* ba  = (const float*)d_in[5];
    const float* Wb1 = (const float*)d_in[6];
    const float* gb1 = (const float*)d_in[7];
    const float* bb1 = (const float*)d_in[8];
    const float* Wb2 = (const float*)d_in[9];
    const float* gb2 = (const float*)d_in[10];
    const float* bb2 = (const float*)d_in[11];
    const float* Wl1 = (const float*)d_in[12];
    const float* gl1 = (const float*)d_in[13];
    const float* bl1 = (const float*)d_in[14];
    const float* Wl2 = (const float*)d_in[15];
    const float* gl2 = (const float*)d_in[16];
    const float* bl2 = (const float*)d_in[17];
    const float* eps1 = (const float*)d_in[18];
    const float* eps2 = (const float*)d_in[19];

    float* out_node = (float*)d_out;
    float* out_edge = out_node + (size_t)NN * HH;

    float *p_lift, *p_y1, *p_lvl, *p_yb1, *p_yl1, *p_wt;
    float *p_sum, *p_sumsq, *p_scale, *p_shift;
    cudaGetSymbolAddress((void**)&p_lift,  g_lift);
    cudaGetSymbolAddress((void**)&p_y1,    g_y1);
    cudaGetSymbolAddress((void**)&p_lvl,   g_lvl);
    cudaGetSymbolAddress((void**)&p_yb1,   g_yb1);
    cudaGetSymbolAddress((void**)&p_yl1,   g_yl1);
    cudaGetSymbolAddress((void**)&p_wt,    g_wt);
    cudaGetSymbolAddress((void**)&p_sum,   g_sum);
    cudaGetSymbolAddress((void**)&p_sumsq, g_sumsq);
    cudaGetSymbolAddress((void**)&p_scale, g_scale);
    cudaGetSymbolAddress((void**)&p_shift, g_shift);

    const int SMEM = 16384 * 4;   // 64 KB dynamic
    cudaFuncSetAttribute(k_gemm_merged,       cudaFuncAttributeMaxDynamicSharedMemorySize, SMEM);
    cudaFuncSetAttribute(k_gemm_mma<2, 128>,  cudaFuncAttributeMaxDynamicSharedMemorySize, SMEM);
    cudaFuncSetAttribute(k_gemm_pair<3, 256>, cudaFuncAttributeMaxDynamicSharedMemorySize, SMEM);

    // 0) prep (folds (1+eps2)Wl1 into merged weight)
    k_prep<<<2048, 256>>>(Wa, Wb1, Wb2, Wl1, Wl2, eps2, p_wt, p_lift, p_lvl, p_sum);

    const int scatter_blocks = (MM * 32 + 255) / 256;
    const int gridE = (EE + 127) / 128;   // 3125
    const int gridN = (NN + 127) / 128;   // 391

    // 1) lift_aggr[dst] += node_rep[src]
    k_scatter<<<scatter_blocks, 256>>>(node_rep, src, dst, p_lift);

    // 2) merged: y1 = cat@Wa, yl1 = (lift+(1+eps2)edge)@Wl1  — one [E,256]@[256,384]
    k_gemm_merged<<<dim3(gridE, 3), 256, SMEM>>>(
        p_lift, edge_rep, p_wt + WT_M, p_y1, p_yl1,
        p_sum + 0, p_sumsq + 0, p_sum + 768, p_sumsq + 768);
    k_finalize2<<<1, 512>>>(128, 1.f / EE, ga, ba, p_sum + 0, p_sumsq + 0,
                            p_scale + 0, p_shift + 0,
                            256, 1.f / EE, gl1, bl1, p_sum + 768, p_sumsq + 768,
                            p_scale + 768, p_shift + 768);

    // 3) lvl_aggr[src] += relu(bn(y1))[dst]
    k_scatter_bn<<<scatter_blocks, 256>>>(p_y1, dst, src, p_scale + 0, p_shift + 0, p_lvl);

    // 4) node GEMM4: yb1 = ((1+eps1)node + lvl) @ Wb1
    k_gemm_mma<2, 128><<<dim3(gridN, 2), 256, SMEM>>>(
        node_rep, p_lvl, nullptr, nullptr, eps1, p_wt + WT_B1,
        p_yb1, NN, 256, p_sum + 256, p_sumsq + 256);
    k_finalize<<<1, 256>>>(256, 1.f / NN, gb1, bb1, p_sum + 256, p_sumsq + 256,
                           p_scale + 256, p_shift + 256);

    // 5) merged GEMM5: edge (->out_edge) + node (->out_node), both MODE3 K=256 NC=128
    k_gemm_pair<3, 256><<<dim3(gridE + gridN, 1), 256, SMEM>>>(
        p_yl1, nullptr, p_scale + 768, p_shift + 768, nullptr, p_wt + WT_L2,
        out_edge, EE, p_sum + 1024, p_sumsq + 1024,
        p_yb1, nullptr, p_scale + 256, p_shift + 256, nullptr, p_wt + WT_B2,
        out_node, NN, p_sum + 512, p_sumsq + 512,
        gridE, 128);
    k_finalize2<<<1, 512>>>(128, 1.f / EE, gl2, bl2, p_sum + 1024, p_sumsq + 1024,
                            p_scale + 1024, p_shift + 1024,
                            128, 1.f / NN, gb2, bb2, p_sum + 512, p_sumsq + 512,
                            p_scale + 512, p_shift + 512);

    // 6) merged final BN-ReLU apply on both outputs
    k_apply2<<<2048, 256>>>(out_edge, (long long)EE * HH / 4, p_scale + 1024, p_shift + 1024,
                            out_node, (long long)NN * HH / 4, p_scale + 512, p_shift + 512);
}

// round 15
// speedup vs baseline: 1.1137x; 1.1137x over previous
#include <cuda_runtime.h>
#include <cstdint>

#define NN 50000
#define EE 400000
#define MM 800000
#define HH 128
#define HM 256
#define BN_EPS 1e-5f

// ---------------- device scratch ----------------
__device__ float g_lift[(size_t)EE * HH];
__device__ float g_y1  [(size_t)EE * HH];
__device__ float g_lvl [(size_t)NN * HH];
__device__ float g_yb1 [(size_t)NN * HM];
__device__ float g_yl1 [(size_t)EE * HM];
__device__ float g_wt  [5 * 32768];          // tf32 weights in B-fragment order
__device__ float g_sum  [5 * 256];
__device__ float g_sumsq[5 * 256];
__device__ float g_scale[5 * 256];
__device__ float g_shift[5 * 256];

// ---------------- helpers ----------------
__device__ __forceinline__ float f2tf(float x) {
    uint32_t r;
    asm("cvt.rna.tf32.f32 %0, %1;" : "=r"(r) : "f"(x));
    return __uint_as_float(r);
}
__device__ __forceinline__ uint32_t smem_u32(const void* p) {
    uint32_t a;
    asm("{ .reg .u64 t; cvta.to.shared.u64 t, %1; cvt.u32.u64 %0, t; }" : "=r"(a) : "l"(p));
    return a;
}
__device__ __forceinline__ void cp_async16(uint32_t d, const void* s) {
    asm volatile("cp.async.ca.shared.global [%0], [%1], 16;" :: "r"(d), "l"(s) : "memory");
}
__device__ __forceinline__ void cp_commit() {
    asm volatile("cp.async.commit_group;" ::: "memory");
}
__device__ __forceinline__ void cp_wait_all() {
    asm volatile("cp.async.wait_group 0;" ::: "memory");
}
__device__ __forceinline__ void mma_tf32(float* c, const uint32_t* a, const uint32_t* b) {
    asm volatile("mma.sync.aligned.m16n8k8.row.col.f32.tf32.tf32.f32 "
                 "{%0,%1,%2,%3}, {%4,%5,%6,%7}, {%8,%9}, {%0,%1,%2,%3};"
                 : "+f"(c[0]), "+f"(c[1]), "+f"(c[2]), "+f"(c[3])
                 : "r"(a[0]), "r"(a[1]), "r"(a[2]), "r"(a[3]),
                   "r"(b[0]), "r"(b[1]));
}
__device__ __forceinline__ void red_add_v4(float* p, float4 v) {
    asm volatile("red.global.add.v4.f32 [%0], {%1,%2,%3,%4};"
                 :: "l"(p), "f"(v.x), "f"(v.y), "f"(v.z), "f"(v.w) : "memory");
}

// ---------------- prep: zero scratch + build fragment-order tf32 weights ----------------
__global__ void k_prep(const float* __restrict__ Wa,  const float* __restrict__ Wb1,
                       const float* __restrict__ Wb2, const float* __restrict__ Wl1,
                       const float* __restrict__ Wl2,
                       float* __restrict__ wfrag,
                       float* __restrict__ lift, float* __restrict__ lvl,
                       float* __restrict__ sums)
{
    long long t = (long long)blockIdx.x * blockDim.x + threadIdx.x;
    const long long stride = (long long)gridDim.x * blockDim.x;
    const long long n1 = (long long)EE * HH / 4;
    for (long long i = t; i < n1; i += stride)
        ((float4*)lift)[i] = make_float4(0.f, 0.f, 0.f, 0.f);
    const long long n2 = (long long)NN * HH / 4;
    for (long long i = t; i < n2; i += stride)
        ((float4*)lvl)[i] = make_float4(0.f, 0.f, 0.f, 0.f);
    if (t < 2560) sums[t] = 0.f;
    for (long long i = t; i < 5 * 32768; i += stride) {
        int w = (int)(i >> 15);
        int e = (int)(i & 32767);
        int K  = (w == 1 || w == 3) ? 128 : 256;
        int NC = 32768 / K;
        int k = e / NC, n = e % NC;
        const float* W = (w == 0) ? Wa : (w == 1) ? Wb1 : (w == 2) ? Wb2 : (w == 3) ? Wl1 : Wl2;
        int ch = k >> 5, klc = k & 31;
        int dst = w * 32768 + ch * NC * 32 + (n >> 3) * 256 + (klc >> 3) * 64 +
                  (n & 7) * 8 + (klc & 3) * 2 + ((klc >> 2) & 1);
        wfrag[dst] = f2tf(W[(size_t)k * NC + n]);
    }
}

// ---------------- scatter: out[sidx[m]] += vals[gidx[m]] (rows of 128) ----------------
__global__ void k_scatter(const float* __restrict__ vals,
                          const int*   __restrict__ gidx,
                          const int*   __restrict__ sidx,
                          float*       __restrict__ out)
{
    int t = blockIdx.x * blockDim.x + threadIdx.x;
    int m = t >> 5;
    if (m >= MM) return;
    int lane = t & 31;
    int g = __ldg(gidx + m);
    int s = __ldg(sidx + m);
    float4 v = *(const float4*)(vals + (size_t)g * HH + lane * 4);
    red_add_v4(out + (size_t)s * HH + lane * 4, v);
}

// ---------------- scatter with fused BN-ReLU on the gathered rows ----------------
__global__ void k_scatter_bn(const float* __restrict__ vals,
                             const int*   __restrict__ gidx,
                             const int*   __restrict__ sidx,
                             const float* __restrict__ scale,
                             const float* __restrict__ shift,
                             float*       __restrict__ out)
{
    int t = blockIdx.x * blockDim.x + threadIdx.x;
    int m = t >> 5;
    if (m >= MM) return;
    int lane = t & 31;
    int g = __ldg(gidx + m);
    int s = __ldg(sidx + m);
    float4 v  = *(const float4*)(vals + (size_t)g * HH + lane * 4);
    float4 sc = *(const float4*)(scale + lane * 4);
    float4 sh = *(const float4*)(shift + lane * 4);
    v.x = fmaxf(fmaf(v.x, sc.x, sh.x), 0.f);
    v.y = fmaxf(fmaf(v.y, sc.y, sh.y), 0.f);
    v.z = fmaxf(fmaf(v.z, sc.z, sh.z), 0.f);
    v.w = fmaxf(fmaf(v.w, sc.w, sh.w), 0.f);
    red_add_v4(out + (size_t)s * HH + lane * 4, v);
}

// ---------------- GEMM mainloop body (R13-proven) ----------------
template <int MODE, int K>
__device__ __forceinline__ void gemm_body(
    const float* __restrict__ A0, const float* __restrict__ A1,
    const float* __restrict__ scl, const float* __restrict__ shf,
    float et,
    const float* __restrict__ Bt,
    float* __restrict__ C, int Rows, int Ncols,
    float* __restrict__ osum, float* __restrict__ osumsq,
    int bx, int by, float* __restrict__ smem, uint32_t sB_u32)
{
    float* __restrict__ sA = smem;          // [2][4096]
    float* __restrict__ sB = smem + 8192;   // [2][4096]

    constexpr int NCH = K / 32;

    int tid = threadIdx.x;
    int lane = tid & 31, wid = tid >> 5;
    int wm = wid >> 1, wn = wid & 1;
    int r0 = bx * 128;
    int c0 = by * 128;

    float4 areg[4];

    auto loadA = [&](int ch) {
        int kt = ch * 32;
#pragma unroll
        for (int i = 0; i < 4; i++) {
            int idx = i * 256 + tid;
            int row = idx >> 3, q = idx & 7;
            int gr = r0 + row, k = kt + q * 4;
            float4 v = make_float4(0.f, 0.f, 0.f, 0.f);
            if (gr < Rows) {
                if (MODE == 1) {
                    const float* s = (k < 128) ? A0 + (size_t)gr * 128 + k
                                               : A1 + (size_t)gr * 128 + (k - 128);
                    v = *(const float4*)s;
                } else if (MODE == 2) {
                    float4 x = *(const float4*)(A0 + (size_t)gr * 128 + k);
                    float4 y = *(const float4*)(A1 + (size_t)gr * 128 + k);
                    v.x = fmaf(et, x.x, y.x); v.y = fmaf(et, x.y, y.y);
                    v.z = fmaf(et, x.z, y.z); v.w = fmaf(et, x.w, y.w);
                } else {
                    float4 r4 = *(const float4*)(A0 + (size_t)gr * K + k);
                    float4 s4 = *(const float4*)(scl + k);
                    float4 h4 = *(const float4*)(shf + k);
                    v.x = fmaxf(fmaf(r4.x, s4.x, h4.x), 0.f);
                    v.y = fmaxf(fmaf(r4.y, s4.y, h4.y), 0.f);
                    v.z = fmaxf(fmaf(r4.z, s4.z, h4.z), 0.f);
                    v.w = fmaxf(fmaf(r4.w, s4.w, h4.w), 0.f);
                }
            }
            areg[i] = v;
        }
    };
    auto stsA = [&](int buf) {
        float* __restrict__ d = sA + buf * 4096;
#pragma unroll
        for (int i = 0; i < 4; i++) {
            int idx = i * 256 + tid;
            int row = idx >> 3, q = idx & 7;
            int mt = row >> 4, ks = q >> 1;
            int r = ((row >> 3) & 1) + 2 * (q & 1);
            int base = ((mt * 4 + ks) * 32 + (row & 7) * 4) * 4 + r;
            d[base + 0 ] = f2tf(areg[i].x);
            d[base + 4 ] = f2tf(areg[i].y);
            d[base + 8 ] = f2tf(areg[i].z);
            d[base + 12] = f2tf(areg[i].w);
        }
    };
    auto cpB = [&](int ch, int buf) {
        const float* __restrict__ src = Bt + (size_t)ch * (Ncols * 32) + c0 * 32;
        uint32_t dst = sB_u32 + buf * 16384;
#pragma unroll
        for (int i = 0; i < 4; i++) {
            int idx = i * 256 + tid;
            cp_async16(dst + idx * 16, src + idx * 4);
        }
        cp_commit();
    };

    float acc[2][8][4];
#pragma unroll
    for (int mt = 0; mt < 2; mt++)
#pragma unroll
        for (int nt = 0; nt < 8; nt++)
#pragma unroll
            for (int r = 0; r < 4; r++) acc[mt][nt][r] = 0.f;

    cpB(0, 0);
    loadA(0);
    stsA(0);
    cp_wait_all();
    __syncthreads();

    for (int ch = 0; ch < NCH; ch++) {
        int buf = ch & 1;
        if (ch + 1 < NCH) { cpB(ch + 1, buf ^ 1); loadA(ch + 1); }
        const float* __restrict__ pa = sA + buf * 4096;
        const float* __restrict__ pb = sB + buf * 4096;
#pragma unroll
        for (int ks = 0; ks < 4; ks++) {
            uint4 av[2];
            uint2 bv[8];
#pragma unroll
            for (int mt = 0; mt < 2; mt++)
                av[mt] = *(const uint4*)(pa + (((wm * 2 + mt) * 4 + ks) * 32 + lane) * 4);
#pragma unroll
            for (int nt = 0; nt < 8; nt++)
                bv[nt] = *(const uint2*)(pb + (((wn * 8 + nt) * 4 + ks) * 32 + lane) * 2);
#pragma unroll
            for (int mt = 0; mt < 2; mt++)
#pragma unroll
                for (int nt = 0; nt < 8; nt++)
                    mma_tf32(acc[mt][nt], (const uint32_t*)&av[mt], (const uint32_t*)&bv[nt]);
        }
        if (ch + 1 < NCH) stsA(buf ^ 1);
        cp_wait_all();
        __syncthreads();
    }

    // ---- epilogue: store C + fused column stats ----
    int g = lane >> 2, t = lane & 3;
#pragma unroll
    for (int mt = 0; mt < 2; mt++) {
        int ra = r0 + wm * 32 + mt * 16 + g;
        int rb = ra + 8;
#pragma unroll
        for (int nt = 0; nt < 8; nt++) {
            int col = c0 + wn * 64 + nt * 8 + 2 * t;
            if (ra < Rows) {
                float2 v = make_float2(acc[mt][nt][0], acc[mt][nt][1]);
                *(float2*)(C + (size_t)ra * Ncols + col) = v;
            }
            if (rb < Rows) {
                float2 v = make_float2(acc[mt][nt][2], acc[mt][nt][3]);
                *(float2*)(C + (size_t)rb * Ncols + col) = v;
            }
        }
    }
#pragma unroll
    for (int nt = 0; nt < 8; nt++) {
#pragma unroll
        for (int p = 0; p < 2; p++) {
            float a0 = acc[0][nt][p],     a1 = acc[0][nt][p + 2];
            float a2 = acc[1][nt][p],     a3 = acc[1][nt][p + 2];
            float s  = a0 + a1 + a2 + a3;
            float ss = a0 * a0 + a1 * a1 + a2 * a2 + a3 * a3;
#pragma unroll
            for (int off = 4; off < 32; off <<= 1) {
                s  += __shfl_xor_sync(0xFFFFFFFFu, s,  off);
                ss += __shfl_xor_sync(0xFFFFFFFFu, ss, off);
            }
            if (g == 0) {
                int col = c0 + wn * 64 + nt * 8 + 2 * t + p;
                atomicAdd(osum + col, s);
                atomicAdd(osumsq + col, ss);
            }
        }
    }
}

// ---------------- single-problem GEMM ----------------
template <int MODE, int K>
__global__ __launch_bounds__(256, 2)
void k_gemm_mma(const float* __restrict__ A0, const float* __restrict__ A1,
                const float* __restrict__ scl, const float* __restrict__ shf,
                const float* __restrict__ epsp,
                const float* __restrict__ Bt,
                float* __restrict__ C, int Rows, int Ncols,
                float* __restrict__ osum, float* __restrict__ osumsq)
{
    extern __shared__ float smem[];
    uint32_t sB_u32 = smem_u32(smem + 8192);
    float et = 1.0f;
    if (MODE == 2) et = 1.0f + *epsp;
    gemm_body<MODE, K>(A0, A1, scl, shf, et, Bt, C, Rows, Ncols, osum, osumsq,
                       blockIdx.x, blockIdx.y, smem, sB_u32);
}

// ---------------- two same-shape MODE3 problems in one grid ----------------
template <int MODE, int K>
__global__ __launch_bounds__(256, 2)
void k_gemm_pair(const float* A0a, const float* A1a, const float* scla, const float* shfa,
                 const float* epsa, const float* Bta, float* Ca, int Rowsa,
                 float* osuma, float* osumsqa,
                 const float* A0b, const float* A1b, const float* sclb, const float* shfb,
                 const float* epsb, const float* Btb, float* Cb, int Rowsb,
                 float* osumb, float* osumsqb,
                 int gxa, int Ncols)
{
    extern __shared__ float smem[];
    uint32_t sB_u32 = smem_u32(smem + 8192);

    const bool isB = (int)blockIdx.x >= gxa;
    const float* __restrict__ A0  = isB ? A0b  : A0a;
    const float* __restrict__ A1  = isB ? A1b  : A1a;
    const float* __restrict__ scl = isB ? sclb : scla;
    const float* __restrict__ shf = isB ? shfb : shfa;
    const float* __restrict__ Bt  = isB ? Btb  : Bta;
    float* __restrict__ C         = isB ? Cb   : Ca;
    float* __restrict__ osum      = isB ? osumb : osuma;
    float* __restrict__ osumsq    = isB ? osumsqb : osumsqa;
    int Rows = isB ? Rowsb : Rowsa;
    int bx   = isB ? (int)blockIdx.x - gxa : (int)blockIdx.x;

    float et = 1.0f;
    if (MODE == 2) et = 1.0f + *(isB ? epsb : epsa);

    gemm_body<MODE, K>(A0, A1, scl, shf, et, Bt, C, Rows, Ncols, osum, osumsq,
                       bx, blockIdx.y, smem, sB_u32);
}

// ---------------- A-resident MODE2 pair: K=128, NC=256, A loaded once ----------------
// SMEM: sA[4][4096] (full 128x128 A, fragment order, 64KB) + sB[2][4096] (32KB)
__global__ __launch_bounds__(256, 2)
void k_gemm_pair_kres(const float* A0a, const float* A1a, const float* epsa, const float* Bta,
                      float* Ca, int Rowsa, float* osuma, float* osumsqa,
                      const float* A0b, const float* A1b, const float* epsb, const float* Btb,
                      float* Cb, int Rowsb, float* osumb, float* osumsqb,
                      int gxa)
{
    extern __shared__ float smem[];
    float* __restrict__ sA = smem;            // [4][4096]
    float* __restrict__ sB = smem + 16384;    // [2][4096]
    uint32_t sB_u32 = smem_u32(sB);

    const bool isB2 = (int)blockIdx.x >= gxa;
    const float* __restrict__ A0 = isB2 ? A0b : A0a;
    const float* __restrict__ A1 = isB2 ? A1b : A1a;
    const float* __restrict__ Bt = isB2 ? Btb : Bta;
    float* __restrict__ C        = isB2 ? Cb  : Ca;
    float* __restrict__ osum     = isB2 ? osumb : osuma;
    float* __restrict__ osumsq   = isB2 ? osumsqb : osumsqa;
    int Rows = isB2 ? Rowsb : Rowsa;
    int bx   = isB2 ? (int)blockIdx.x - gxa : (int)blockIdx.x;
    float et = 1.0f + *(isB2 ? epsb : epsa);

    int tid = threadIdx.x;
    int lane = tid & 31, wid = tid >> 5;
    int wm = wid >> 1, wn = wid & 1;
    int r0 = bx * 128;

    auto cpB = [&](int s, int buf) {         // s = half*4 + ch
        int half = s >> 2, ch = s & 3;
        const float* __restrict__ src = Bt + (size_t)ch * (256 * 32) + (half * 128) * 32;
        uint32_t dst = sB_u32 + buf * 16384;
#pragma unroll
        for (int i = 0; i < 4; i++) {
            int idx = i * 256 + tid;
            cp_async16(dst + idx * 16, src + idx * 4);
        }
        cp_commit();
    };

    cpB(0, 0);
    // load FULL A tile (4 chunks) into fragment-order SMEM, transform fused
#pragma unroll
    for (int ch = 0; ch < 4; ch++) {
        int kt = ch * 32;
#pragma unroll
        for (int i = 0; i < 4; i++) {
            int idx = i * 256 + tid;
            int row = idx >> 3, q = idx & 7;
            int gr = r0 + row, k = kt + q * 4;
            float4 v = make_float4(0.f, 0.f, 0.f, 0.f);
            if (gr < Rows) {
                float4 x = *(const float4*)(A0 + (size_t)gr * 128 + k);
                float4 y = *(const float4*)(A1 + (size_t)gr * 128 + k);
                v.x = fmaf(et, x.x, y.x); v.y = fmaf(et, x.y, y.y);
                v.z = fmaf(et, x.z, y.z); v.w = fmaf(et, x.w, y.w);
            }
            int mt = row >> 4, ks = q >> 1;
            int r = ((row >> 3) & 1) + 2 * (q & 1);
            int base = ch * 4096 + ((mt * 4 + ks) * 32 + (row & 7) * 4) * 4 + r;
            sA[base + 0 ] = f2tf(v.x);
            sA[base + 4 ] = f2tf(v.y);
            sA[base + 8 ] = f2tf(v.z);
            sA[base + 12] = f2tf(v.w);
        }
    }
    cp_wait_all();
    __syncthreads();

    float acc[2][8][4];
    int g = lane >> 2, t4 = lane & 3;

    for (int half = 0; half < 2; half++) {
#pragma unroll
        for (int mt = 0; mt < 2; mt++)
#pragma unroll
            for (int nt = 0; nt < 8; nt++)
#pragma unroll
                for (int r = 0; r < 4; r++) acc[mt][nt][r] = 0.f;

        for (int ch = 0; ch < 4; ch++) {
            int s = half * 4 + ch;
            int buf = s & 1;
            if (s < 7) cpB(s + 1, buf ^ 1);
            const float* __restrict__ pa = sA + ch * 4096;
            const float* __restrict__ pb = sB + buf * 4096;
#pragma unroll
            for (int ks = 0; ks < 4; ks++) {
                uint4 av[2];
                uint2 bv[8];
#pragma unroll
                for (int mt = 0; mt < 2; mt++)
                    av[mt] = *(const uint4*)(pa + (((wm * 2 + mt) * 4 + ks) * 32 + lane) * 4);
#pragma unroll
                for (int nt = 0; nt < 8; nt++)
                    bv[nt] = *(const uint2*)(pb + (((wn * 8 + nt) * 4 + ks) * 32 + lane) * 2);
#pragma unroll
                for (int mt = 0; mt < 2; mt++)
#pragma unroll
                    for (int nt = 0; nt < 8; nt++)
                        mma_tf32(acc[mt][nt], (const uint32_t*)&av[mt], (const uint32_t*)&bv[nt]);
            }
            cp_wait_all();
            __syncthreads();
        }

        // epilogue for this half: C columns [half*128, +128), stride 256
        int c0C = half * 128;
#pragma unroll
        for (int mt = 0; mt < 2; mt++) {
            int ra = r0 + wm * 32 + mt * 16 + g;
            int rb = ra + 8;
#pragma unroll
            for (int nt = 0; nt < 8; nt++) {
                int col = c0C + wn * 64 + nt * 8 + 2 * t4;
                if (ra < Rows) {
                    float2 v = make_float2(acc[mt][nt][0], acc[mt][nt][1]);
                    *(float2*)(C + (size_t)ra * 256 + col) = v;
                }
                if (rb < Rows) {
                    float2 v = make_float2(acc[mt][nt][2], acc[mt][nt][3]);
                    *(float2*)(C + (size_t)rb * 256 + col) = v;
                }
            }
        }
#pragma unroll
        for (int nt = 0; nt < 8; nt++) {
#pragma unroll
            for (int p = 0; p < 2; p++) {
                float a0 = acc[0][nt][p],     a1 = acc[0][nt][p + 2];
                float a2 = acc[1][nt][p],     a3 = acc[1][nt][p + 2];
                float s  = a0 + a1 + a2 + a3;
                float ss = a0 * a0 + a1 * a1 + a2 * a2 + a3 * a3;
#pragma unroll
                for (int off = 4; off < 32; off <<= 1) {
                    s  += __shfl_xor_sync(0xFFFFFFFFu, s,  off);
                    ss += __shfl_xor_sync(0xFFFFFFFFu, ss, off);
                }
                if (g == 0) {
                    int col = c0C + wn * 64 + nt * 8 + 2 * t4 + p;
                    atomicAdd(osum + col, s);
                    atomicAdd(osumsq + col, ss);
                }
            }
        }
    }
}

// ---------------- BN scale/shift from sums (single) ----------------
__global__ void k_finalize(int C, float invR,
                           const float* __restrict__ g, const float* __restrict__ b,
                           const float* __restrict__ sum, const float* __restrict__ sumsq,
                           float* __restrict__ scale, float* __restrict__ shift)
{
    int c = threadIdx.x;
    if (c < C) {
        float m   = sum[c] * invR;
        float var = sumsq[c] * invR - m * m;
        float s   = g[c] * rsqrtf(var + BN_EPS);
        scale[c] = s;
        shift[c] = b[c] - m * s;
    }
}

// ---------------- BN scale/shift for two norms in one launch (512 threads) ----------------
__global__ void k_finalize2(int C1, float invR1, const float* __restrict__ g1,
                            const float* __restrict__ b1, const float* __restrict__ sum1,
                            const float* __restrict__ sumsq1, float* __restrict__ scale1,
                            float* __restrict__ shift1,
                            int C2, float invR2, const float* __restrict__ g2,
                            const float* __restrict__ b2, const float* __restrict__ sum2,
                            const float* __restrict__ sumsq2, float* __restrict__ scale2,
                            float* __restrict__ shift2)
{
    int t = threadIdx.x;
    if (t < 256) {
        if (t < C1) {
            float m   = sum1[t] * invR1;
            float var = sumsq1[t] * invR1 - m * m;
            float s   = g1[t] * rsqrtf(var + BN_EPS);
            scale1[t] = s;
            shift1[t] = b1[t] - m * s;
        }
    } else {
        int c = t - 256;
        if (c < C2) {
            float m   = sum2[c] * invR2;
            float var = sumsq2[c] * invR2 - m * m;
            float s   = g2[c] * rsqrtf(var + BN_EPS);
            scale2[c] = s;
            shift2[c] = b2[c] - m * s;
        }
    }
}

// ---------------- in-place BN affine + ReLU for two tensors ----------------
__global__ void k_apply2(float* __restrict__ X1, long long n4_1,
                         const float* __restrict__ scale1, const float* __restrict__ shift1,
                         float* __restrict__ X2, long long n4_2,
                         const float* __restrict__ scale2, const float* __restrict__ shift2)
{
    long long total = n4_1 + n4_2;
    for (long long idx = blockIdx.x * (long long)blockDim.x + threadIdx.x; idx < total;
         idx += (long long)gridDim.x * blockDim.x) {
        float* X; const float *scale, *shift; long long i;
        if (idx < n4_1) { X = X1; scale = scale1; shift = shift1; i = idx; }
        else            { X = X2; scale = scale2; shift = shift2; i = idx - n4_1; }
        int c4 = (int)(i & 31);
        float4 v  = ((float4*)X)[i];
        float4 sc = *(const float4*)(scale + c4 * 4);
        float4 sh = *(const float4*)(shift + c4 * 4);
        v.x = fmaxf(fmaf(v.x, sc.x, sh.x), 0.f);
        v.y = fmaxf(fmaf(v.y, sc.y, sh.y), 0.f);
        v.z = fmaxf(fmaf(v.z, sc.z, sh.z), 0.f);
        v.w = fmaxf(fmaf(v.w, sc.w, sh.w), 0.f);
        ((float4*)X)[i] = v;
    }
}

// ---------------- launch ----------------
extern "C" void kernel_launch(void* const* d_in, const int* in_sizes, int n_in,
                              void* d_out, int out_size)
{
    const float* node_rep = (const float*)d_in[0];
    const float* edge_rep = (const float*)d_in[1];
    const int*   n2e      = (const int*)  d_in[2];
    const int*   src = n2e;
    const int*   dst = n2e + MM;
    const float* Wa  = (const float*)d_in[3];
    const float* ga  = (const float*)d_in[4];
    const float* ba  = (const float*)d_in[5];
    const float* Wb1 = (const float*)d_in[6];
    const float* gb1 = (const float*)d_in[7];
    const float* bb1 = (const float*)d_in[8];
    const float* Wb2 = (const float*)d_in[9];
    const float* gb2 = (const float*)d_in[10];
    const float* bb2 = (const float*)d_in[11];
    const float* Wl1 = (const float*)d_in[12];
    const float* gl1 = (const float*)d_in[13];
    const float* bl1 = (const float*)d_in[14];
    const float* Wl2 = (const float*)d_in[15];
    const float* gl2 = (const float*)d_in[16];
    const float* bl2 = (const float*)d_in[17];
    const float* eps1 = (const float*)d_in[18];
    const float* eps2 = (const float*)d_in[19];

    float* out_node = (float*)d_out;
    float* out_edge = out_node + (size_t)NN * HH;

    float *p_lift, *p_y1, *p_lvl, *p_yb1, *p_yl1, *p_wt;
    float *p_sum, *p_sumsq, *p_scale, *p_shift;
    cudaGetSymbolAddress((void**)&p_lift,  g_lift);
    cudaGetSymbolAddress((void**)&p_y1,    g_y1);
    cudaGetSymbolAddress((void**)&p_lvl,   g_lvl);
    cudaGetSymbolAddress((void**)&p_yb1,   g_yb1);
    cudaGetSymbolAddress((void**)&p_yl1,   g_yl1);
    cudaGetSymbolAddress((void**)&p_wt,    g_wt);
    cudaGetSymbolAddress((void**)&p_sum,   g_sum);
    cudaGetSymbolAddress((void**)&p_sumsq, g_sumsq);
    cudaGetSymbolAddress((void**)&p_scale, g_scale);
    cudaGetSymbolAddress((void**)&p_shift, g_shift);

    const int SMEM  = 16384 * 4;   // 64 KB (standard GEMMs)
    const int SMEMK = 98304;       // 96 KB (A-resident MODE2 pair)
    cudaFuncSetAttribute(k_gemm_mma<1, 256>,  cudaFuncAttributeMaxDynamicSharedMemorySize, SMEM);
    cudaFuncSetAttribute(k_gemm_pair_kres,    cudaFuncAttributeMaxDynamicSharedMemorySize, SMEMK);
    cudaFuncSetAttribute(k_gemm_pair<3, 256>, cudaFuncAttributeMaxDynamicSharedMemorySize, SMEM);

    // 0) prep
    k_prep<<<2048, 256>>>(Wa, Wb1, Wb2, Wl1, Wl2, p_wt, p_lift, p_lvl, p_sum);

    const int scatter_blocks = (MM * 32 + 255) / 256;
    const int gridE = (EE + 127) / 128;   // 3125
    const int gridN = (NN + 127) / 128;   // 391

    // 1) lift_aggr[dst] += node_rep[src]
    k_scatter<<<scatter_blocks, 256>>>(node_rep, src, dst, p_lift);

    // 2) y1 = concat(lift, edge) @ Wa  [E,128]
    k_gemm_mma<1, 256><<<dim3(gridE, 1), 256, SMEM>>>(
        p_lift, edge_rep, nullptr, nullptr, nullptr, p_wt + 0 * 32768,
        p_y1, EE, 128, p_sum + 0, p_sumsq + 0);
    k_finalize<<<1, 256>>>(128, 1.f / EE, ga, ba, p_sum + 0, p_sumsq + 0, p_scale + 0, p_shift + 0);

    // 3) lvl_aggr[src] += relu(bn(y1))[dst]
    k_scatter_bn<<<scatter_blocks, 256>>>(p_y1, dst, src, p_scale + 0, p_shift + 0, p_lvl);

    // 4) merged GEMM4 (A-resident): edge (he@Wl1) + node (hn@Wb1)
    k_gemm_pair_kres<<<dim3(gridE + gridN, 1), 256, SMEMK>>>(
        edge_rep, p_lift, eps2, p_wt + 3 * 32768,
        p_yl1, EE, p_sum + 768, p_sumsq + 768,
        node_rep, p_lvl, eps1, p_wt + 1 * 32768,
        p_yb1, NN, p_sum + 256, p_sumsq + 256,
        gridE);
    k_finalize2<<<1, 512>>>(256, 1.f / EE, gl1, bl1, p_sum + 768, p_sumsq + 768,
                            p_scale + 768, p_shift + 768,
                            256, 1.f / NN, gb1, bb1, p_sum + 256, p_sumsq + 256,
                            p_scale + 256, p_shift + 256);

    // 5) merged GEMM5: edge (->out_edge) + node (->out_node), both MODE3 K=256 NC=128
    k_gemm_pair<3, 256><<<dim3(gridE + gridN, 1), 256, SMEM>>>(
        p_yl1, nullptr, p_scale + 768, p_shift + 768, nullptr, p_wt + 4 * 32768,
        out_edge, EE, p_sum + 1024, p_sumsq + 1024,
        p_yb1, nullptr, p_scale + 256, p_shift + 256, nullptr, p_wt + 2 * 32768,
        out_node, NN, p_sum + 512, p_sumsq + 512,
        gridE, 128);
    k_finalize2<<<1, 512>>>(128, 1.f / EE, gl2, bl2, p_sum + 1024, p_sumsq + 1024,
                            p_scale + 1024, p_shift + 1024,
                            128, 1.f / NN, gb2, bb2, p_sum + 512, p_sumsq + 512,
                            p_scale + 512, p_shift + 512);

    // 6) merged final BN-ReLU apply on both outputs
    k_apply2<<<2048, 256>>>(out_edge, (long long)EE * HH / 4, p_scale + 1024, p_shift + 1024,
                            out_node, (long long)NN * HH / 4, p_scale + 512, p_shift + 512);
}

// round 16
// speedup vs baseline: 1.1808x; 1.0603x over previous
#include <cuda_runtime.h>
#include <cstdint>

#define NN 50000
#define EE 400000
#define MM 800000
#define HH 128
#define HM 256
#define BN_EPS 1e-5f

// ---------------- device scratch ----------------
__device__ float g_lift[(size_t)EE * HH];
__device__ float g_y1  [(size_t)EE * HH];
__device__ float g_lvl [(size_t)NN * HH];
__device__ float g_yb1 [(size_t)NN * HM];
__device__ float g_yl1 [(size_t)EE * HM];
__device__ float g_wt  [5 * 32768];          // tf32 weights in B-fragment order
__device__ float g_sum  [5 * 256];
__device__ float g_sumsq[5 * 256];
__device__ float g_scale[5 * 256];
__device__ float g_shift[5 * 256];

// ---------------- helpers ----------------
__device__ __forceinline__ float f2tf(float x) {
    uint32_t r;
    asm("cvt.rna.tf32.f32 %0, %1;" : "=r"(r) : "f"(x));
    return __uint_as_float(r);
}
__device__ __forceinline__ uint32_t smem_u32(const void* p) {
    uint32_t a;
    asm("{ .reg .u64 t; cvta.to.shared.u64 t, %1; cvt.u32.u64 %0, t; }" : "=r"(a) : "l"(p));
    return a;
}
__device__ __forceinline__ void cp_async16(uint32_t d, const void* s) {
    asm volatile("cp.async.ca.shared.global [%0], [%1], 16;" :: "r"(d), "l"(s) : "memory");
}
__device__ __forceinline__ void cp_commit() {
    asm volatile("cp.async.commit_group;" ::: "memory");
}
__device__ __forceinline__ void cp_wait_all() {
    asm volatile("cp.async.wait_group 0;" ::: "memory");
}
__device__ __forceinline__ void mma_tf32(float* c, const uint32_t* a, const uint32_t* b) {
    asm volatile("mma.sync.aligned.m16n8k8.row.col.f32.tf32.tf32.f32 "
                 "{%0,%1,%2,%3}, {%4,%5,%6,%7}, {%8,%9}, {%0,%1,%2,%3};"
                 : "+f"(c[0]), "+f"(c[1]), "+f"(c[2]), "+f"(c[3])
                 : "r"(a[0]), "r"(a[1]), "r"(a[2]), "r"(a[3]),
                   "r"(b[0]), "r"(b[1]));
}
__device__ __forceinline__ void red_add_v4(float* p, float4 v) {
    asm volatile("red.global.add.v4.f32 [%0], {%1,%2,%3,%4};"
                 :: "l"(p), "f"(v.x), "f"(v.y), "f"(v.z), "f"(v.w) : "memory");
}

// ---------------- prep: zero scratch + build fragment-order tf32 weights ----------------
__global__ void k_prep(const float* __restrict__ Wa,  const float* __restrict__ Wb1,
                       const float* __restrict__ Wb2, const float* __restrict__ Wl1,
                       const float* __restrict__ Wl2,
                       float* __restrict__ wfrag,
                       float* __restrict__ lift, float* __restrict__ lvl,
                       float* __restrict__ sums)
{
    long long t = (long long)blockIdx.x * blockDim.x + threadIdx.x;
    const long long stride = (long long)gridDim.x * blockDim.x;
    const long long n1 = (long long)EE * HH / 4;
    for (long long i = t; i < n1; i += stride)
        ((float4*)lift)[i] = make_float4(0.f, 0.f, 0.f, 0.f);
    const long long n2 = (long long)NN * HH / 4;
    for (long long i = t; i < n2; i += stride)
        ((float4*)lvl)[i] = make_float4(0.f, 0.f, 0.f, 0.f);
    if (t < 2560) sums[t] = 0.f;
    for (long long i = t; i < 5 * 32768; i += stride) {
        int w = (int)(i >> 15);
        int e = (int)(i & 32767);
        int K  = (w == 1 || w == 3) ? 128 : 256;
        int NC = 32768 / K;
        int k = e / NC, n = e % NC;
        const float* W = (w == 0) ? Wa : (w == 1) ? Wb1 : (w == 2) ? Wb2 : (w == 3) ? Wl1 : Wl2;
        int ch = k >> 5, klc = k & 31;
        int dst = w * 32768 + ch * NC * 32 + (n >> 3) * 256 + (klc >> 3) * 64 +
                  (n & 7) * 8 + (klc & 3) * 2 + ((klc >> 2) & 1);
        wfrag[dst] = f2tf(W[(size_t)k * NC + n]);
    }
}

// ---------------- scatter: out[sidx[m]] += vals[gidx[m]] (rows of 128) ----------------
__global__ void k_scatter(const float* __restrict__ vals,
                          const int*   __restrict__ gidx,
                          const int*   __restrict__ sidx,
                          float*       __restrict__ out)
{
    int t = blockIdx.x * blockDim.x + threadIdx.x;
    int m = t >> 5;
    if (m >= MM) return;
    int lane = t & 31;
    int g = __ldg(gidx + m);
    int s = __ldg(sidx + m);
    float4 v = *(const float4*)(vals + (size_t)g * HH + lane * 4);
    red_add_v4(out + (size_t)s * HH + lane * 4, v);
}

// ---------------- scatter with fused BN-ReLU on the gathered rows ----------------
__global__ void k_scatter_bn(const float* __restrict__ vals,
                             const int*   __restrict__ gidx,
                             const int*   __restrict__ sidx,
                             const float* __restrict__ scale,
                             const float* __restrict__ shift,
                             float*       __restrict__ out)
{
    int t = blockIdx.x * blockDim.x + threadIdx.x;
    int m = t >> 5;
    if (m >= MM) return;
    int lane = t & 31;
    int g = __ldg(gidx + m);
    int s = __ldg(sidx + m);
    float4 v  = *(const float4*)(vals + (size_t)g * HH + lane * 4);
    float4 sc = *(const float4*)(scale + lane * 4);
    float4 sh = *(const float4*)(shift + lane * 4);
    v.x = fmaxf(fmaf(v.x, sc.x, sh.x), 0.f);
    v.y = fmaxf(fmaf(v.y, sc.y, sh.y), 0.f);
    v.z = fmaxf(fmaf(v.z, sc.z, sh.z), 0.f);
    v.w = fmaxf(fmaf(v.w, sc.w, sh.w), 0.f);
    red_add_v4(out + (size_t)s * HH + lane * 4, v);
}

// ---------------- GEMM mainloop body (R13-proven) ----------------
template <int MODE, int K>
__device__ __forceinline__ void gemm_body(
    const float* __restrict__ A0, const float* __restrict__ A1,
    const float* __restrict__ scl, const float* __restrict__ shf,
    float et,
    const float* __restrict__ Bt,
    float* __restrict__ C, int Rows, int Ncols,
    float* __restrict__ osum, float* __restrict__ osumsq,
    int bx, int by, float* __restrict__ smem, uint32_t sB_u32)
{
    float* __restrict__ sA = smem;          // [2][4096]
    float* __restrict__ sB = smem + 8192;   // [2][4096]

    constexpr int NCH = K / 32;

    int tid = threadIdx.x;
    int lane = tid & 31, wid = tid >> 5;
    int wm = wid >> 1, wn = wid & 1;
    int r0 = bx * 128;
    int c0 = by * 128;

    float4 areg[4];

    auto loadA = [&](int ch) {
        int kt = ch * 32;
#pragma unroll
        for (int i = 0; i < 4; i++) {
            int idx = i * 256 + tid;
            int row = idx >> 3, q = idx & 7;
            int gr = r0 + row, k = kt + q * 4;
            float4 v = make_float4(0.f, 0.f, 0.f, 0.f);
            if (gr < Rows) {
                if (MODE == 1) {
                    const float* s = (k < 128) ? A0 + (size_t)gr * 128 + k
                                               : A1 + (size_t)gr * 128 + (k - 128);
                    v = *(const float4*)s;
                } else if (MODE == 2) {
                    float4 x = *(const float4*)(A0 + (size_t)gr * 128 + k);
                    float4 y = *(const float4*)(A1 + (size_t)gr * 128 + k);
                    v.x = fmaf(et, x.x, y.x); v.y = fmaf(et, x.y, y.y);
                    v.z = fmaf(et, x.z, y.z); v.w = fmaf(et, x.w, y.w);
                } else {
                    float4 r4 = *(const float4*)(A0 + (size_t)gr * K + k);
                    float4 s4 = *(const float4*)(scl + k);
                    float4 h4 = *(const float4*)(shf + k);
                    v.x = fmaxf(fmaf(r4.x, s4.x, h4.x), 0.f);
                    v.y = fmaxf(fmaf(r4.y, s4.y, h4.y), 0.f);
                    v.z = fmaxf(fmaf(r4.z, s4.z, h4.z), 0.f);
                    v.w = fmaxf(fmaf(r4.w, s4.w, h4.w), 0.f);
                }
            }
            areg[i] = v;
        }
    };
    auto stsA = [&](int buf) {
        float* __restrict__ d = sA + buf * 4096;
#pragma unroll
        for (int i = 0; i < 4; i++) {
            int idx = i * 256 + tid;
            int row = idx >> 3, q = idx & 7;
            int mt = row >> 4, ks = q >> 1;
            int r = ((row >> 3) & 1) + 2 * (q & 1);
            int base = ((mt * 4 + ks) * 32 + (row & 7) * 4) * 4 + r;
            d[base + 0 ] = f2tf(areg[i].x);
            d[base + 4 ] = f2tf(areg[i].y);
            d[base + 8 ] = f2tf(areg[i].z);
            d[base + 12] = f2tf(areg[i].w);
        }
    };
    auto cpB = [&](int ch, int buf) {
        const float* __restrict__ src = Bt + (size_t)ch * (Ncols * 32) + c0 * 32;
        uint32_t dst = sB_u32 + buf * 16384;
#pragma unroll
        for (int i = 0; i < 4; i++) {
            int idx = i * 256 + tid;
            cp_async16(dst + idx * 16, src + idx * 4);
        }
        cp_commit();
    };

    float acc[2][8][4];
#pragma unroll
    for (int mt = 0; mt < 2; mt++)
#pragma unroll
        for (int nt = 0; nt < 8; nt++)
#pragma unroll
            for (int r = 0; r < 4; r++) acc[mt][nt][r] = 0.f;

    cpB(0, 0);
    loadA(0);
    stsA(0);
    cp_wait_all();
    __syncthreads();

    for (int ch = 0; ch < NCH; ch++) {
        int buf = ch & 1;
        if (ch + 1 < NCH) { cpB(ch + 1, buf ^ 1); loadA(ch + 1); }
        const float* __restrict__ pa = sA + buf * 4096;
        const float* __restrict__ pb = sB + buf * 4096;
#pragma unroll
        for (int ks = 0; ks < 4; ks++) {
            uint4 av[2];
            uint2 bv[8];
#pragma unroll
            for (int mt = 0; mt < 2; mt++)
                av[mt] = *(const uint4*)(pa + (((wm * 2 + mt) * 4 + ks) * 32 + lane) * 4);
#pragma unroll
            for (int nt = 0; nt < 8; nt++)
                bv[nt] = *(const uint2*)(pb + (((wn * 8 + nt) * 4 + ks) * 32 + lane) * 2);
#pragma unroll
            for (int mt = 0; mt < 2; mt++)
#pragma unroll
                for (int nt = 0; nt < 8; nt++)
                    mma_tf32(acc[mt][nt], (const uint32_t*)&av[mt], (const uint32_t*)&bv[nt]);
        }
        if (ch + 1 < NCH) stsA(buf ^ 1);
        cp_wait_all();
        __syncthreads();
    }

    // ---- epilogue: store C + fused column stats ----
    int g = lane >> 2, t = lane & 3;
#pragma unroll
    for (int mt = 0; mt < 2; mt++) {
        int ra = r0 + wm * 32 + mt * 16 + g;
        int rb = ra + 8;
#pragma unroll
        for (int nt = 0; nt < 8; nt++) {
            int col = c0 + wn * 64 + nt * 8 + 2 * t;
            if (ra < Rows) {
                float2 v = make_float2(acc[mt][nt][0], acc[mt][nt][1]);
                *(float2*)(C + (size_t)ra * Ncols + col) = v;
            }
            if (rb < Rows) {
                float2 v = make_float2(acc[mt][nt][2], acc[mt][nt][3]);
                *(float2*)(C + (size_t)rb * Ncols + col) = v;
            }
        }
    }
#pragma unroll
    for (int nt = 0; nt < 8; nt++) {
#pragma unroll
        for (int p = 0; p < 2; p++) {
            float a0 = acc[0][nt][p],     a1 = acc[0][nt][p + 2];
            float a2 = acc[1][nt][p],     a3 = acc[1][nt][p + 2];
            float s  = a0 + a1 + a2 + a3;
            float ss = a0 * a0 + a1 * a1 + a2 * a2 + a3 * a3;
#pragma unroll
            for (int off = 4; off < 32; off <<= 1) {
                s  += __shfl_xor_sync(0xFFFFFFFFu, s,  off);
                ss += __shfl_xor_sync(0xFFFFFFFFu, ss, off);
            }
            if (g == 0) {
                int col = c0 + wn * 64 + nt * 8 + 2 * t + p;
                atomicAdd(osum + col, s);
                atomicAdd(osumsq + col, ss);
            }
        }
    }
}

// ---------------- A-resident MODE2 body: K=128, NC=256, A loaded once ----------------
// SMEM: sA[4][4096] (64KB) + sB[2][4096] (32KB)
__device__ __forceinline__ void kres_body(
    const float* __restrict__ A0, const float* __restrict__ A1, float et,
    const float* __restrict__ Bt,
    float* __restrict__ C, int Rows,
    float* __restrict__ osum, float* __restrict__ osumsq,
    int bx, float* __restrict__ smem)
{
    float* __restrict__ sA = smem;            // [4][4096]
    float* __restrict__ sB = smem + 16384;    // [2][4096]
    uint32_t sB_u32 = smem_u32(sB);

    int tid = threadIdx.x;
    int lane = tid & 31, wid = tid >> 5;
    int wm = wid >> 1, wn = wid & 1;
    int r0 = bx * 128;

    auto cpB = [&](int s, int buf) {         // s = half*4 + ch
        int half = s >> 2, ch = s & 3;
        const float* __restrict__ src = Bt + (size_t)ch * (256 * 32) + (half * 128) * 32;
        uint32_t dst = sB_u32 + buf * 16384;
#pragma unroll
        for (int i = 0; i < 4; i++) {
            int idx = i * 256 + tid;
            cp_async16(dst + idx * 16, src + idx * 4);
        }
        cp_commit();
    };

    cpB(0, 0);
#pragma unroll
    for (int ch = 0; ch < 4; ch++) {
        int kt = ch * 32;
#pragma unroll
        for (int i = 0; i < 4; i++) {
            int idx = i * 256 + tid;
            int row = idx >> 3, q = idx & 7;
            int gr = r0 + row, k = kt + q * 4;
            float4 v = make_float4(0.f, 0.f, 0.f, 0.f);
            if (gr < Rows) {
                float4 x = *(const float4*)(A0 + (size_t)gr * 128 + k);
                float4 y = *(const float4*)(A1 + (size_t)gr * 128 + k);
                v.x = fmaf(et, x.x, y.x); v.y = fmaf(et, x.y, y.y);
                v.z = fmaf(et, x.z, y.z); v.w = fmaf(et, x.w, y.w);
            }
            int mt = row >> 4, ks = q >> 1;
            int r = ((row >> 3) & 1) + 2 * (q & 1);
            int base = ch * 4096 + ((mt * 4 + ks) * 32 + (row & 7) * 4) * 4 + r;
            sA[base + 0 ] = f2tf(v.x);
            sA[base + 4 ] = f2tf(v.y);
            sA[base + 8 ] = f2tf(v.z);
            sA[base + 12] = f2tf(v.w);
        }
    }
    cp_wait_all();
    __syncthreads();

    float acc[2][8][4];
    int g = lane >> 2, t4 = lane & 3;

    for (int half = 0; half < 2; half++) {
#pragma unroll
        for (int mt = 0; mt < 2; mt++)
#pragma unroll
            for (int nt = 0; nt < 8; nt++)
#pragma unroll
                for (int r = 0; r < 4; r++) acc[mt][nt][r] = 0.f;

        for (int ch = 0; ch < 4; ch++) {
            int s = half * 4 + ch;
            int buf = s & 1;
            if (s < 7) cpB(s + 1, buf ^ 1);
            const float* __restrict__ pa = sA + ch * 4096;
            const float* __restrict__ pb = sB + buf * 4096;
#pragma unroll
            for (int ks = 0; ks < 4; ks++) {
                uint4 av[2];
                uint2 bv[8];
#pragma unroll
                for (int mt = 0; mt < 2; mt++)
                    av[mt] = *(const uint4*)(pa + (((wm * 2 + mt) * 4 + ks) * 32 + lane) * 4);
#pragma unroll
                for (int nt = 0; nt < 8; nt++)
                    bv[nt] = *(const uint2*)(pb + (((wn * 8 + nt) * 4 + ks) * 32 + lane) * 2);
#pragma unroll
                for (int mt = 0; mt < 2; mt++)
#pragma unroll
                    for (int nt = 0; nt < 8; nt++)
                        mma_tf32(acc[mt][nt], (const uint32_t*)&av[mt], (const uint32_t*)&bv[nt]);
            }
            cp_wait_all();
            __syncthreads();
        }

        int c0C = half * 128;
#pragma unroll
        for (int mt = 0; mt < 2; mt++) {
            int ra = r0 + wm * 32 + mt * 16 + g;
            int rb = ra + 8;
#pragma unroll
            for (int nt = 0; nt < 8; nt++) {
                int col = c0C + wn * 64 + nt * 8 + 2 * t4;
                if (ra < Rows) {
                    float2 v = make_float2(acc[mt][nt][0], acc[mt][nt][1]);
                    *(float2*)(C + (size_t)ra * 256 + col) = v;
                }
                if (rb < Rows) {
                    float2 v = make_float2(acc[mt][nt][2], acc[mt][nt][3]);
                    *(float2*)(C + (size_t)rb * 256 + col) = v;
                }
            }
        }
#pragma unroll
        for (int nt = 0; nt < 8; nt++) {
#pragma unroll
            for (int p = 0; p < 2; p++) {
                float a0 = acc[0][nt][p],     a1 = acc[0][nt][p + 2];
                float a2 = acc[1][nt][p],     a3 = acc[1][nt][p + 2];
                float s  = a0 + a1 + a2 + a3;
                float ss = a0 * a0 + a1 * a1 + a2 * a2 + a3 * a3;
#pragma unroll
                for (int off = 4; off < 32; off <<= 1) {
                    s  += __shfl_xor_sync(0xFFFFFFFFu, s,  off);
                    ss += __shfl_xor_sync(0xFFFFFFFFu, ss, off);
                }
                if (g == 0) {
                    int col = c0C + wn * 64 + nt * 8 + 2 * t4 + p;
                    atomicAdd(osum + col, s);
                    atomicAdd(osumsq + col, ss);
                }
            }
        }
    }
}

// ---------------- fused GEMM2 + GEMM4-edge: interleaved for L2 A-reuse ----------------
// bx even -> y1 = [lift|edge]@Wa (row block bx/2);  bx odd -> yl1 = ((1+eps2)edge+lift)@Wl1
__global__ __launch_bounds__(256, 2)
void k_fused2(const float* __restrict__ lift, const float* __restrict__ edge,
              const float* __restrict__ WaF, const float* __restrict__ Wl1F,
              const float* __restrict__ eps2p,
              float* __restrict__ y1, float* __restrict__ yl1,
              float* __restrict__ sum0, float* __restrict__ sumsq0,
              float* __restrict__ suml, float* __restrict__ sumsql)
{
    extern __shared__ float smem[];
    int pairIdx = blockIdx.x >> 1;
    if ((blockIdx.x & 1) == 0) {
        gemm_body<1, 256>(lift, edge, nullptr, nullptr, 1.0f, WaF,
                          y1, EE, 128, sum0, sumsq0,
                          pairIdx, 0, smem, smem_u32(smem + 8192));
    } else {
        float et = 1.0f + *eps2p;
        kres_body(edge, lift, et, Wl1F, yl1, EE, suml, sumsql, pairIdx, smem);
    }
}

// ---------------- A-resident MODE2 pair kernel (node-only use) ----------------
__global__ __launch_bounds__(256, 2)
void k_gemm_pair_kres(const float* A0a, const float* A1a, const float* epsa, const float* Bta,
                      float* Ca, int Rowsa, float* osuma, float* osumsqa,
                      const float* A0b, const float* A1b, const float* epsb, const float* Btb,
                      float* Cb, int Rowsb, float* osumb, float* osumsqb,
                      int gxa)
{
    extern __shared__ float smem[];
    const bool isB2 = (int)blockIdx.x >= gxa;
    const float* __restrict__ A0 = isB2 ? A0b : A0a;
    const float* __restrict__ A1 = isB2 ? A1b : A1a;
    const float* __restrict__ Bt = isB2 ? Btb : Bta;
    float* __restrict__ C        = isB2 ? Cb  : Ca;
    float* __restrict__ osum     = isB2 ? osumb : osuma;
    float* __restrict__ osumsq   = isB2 ? osumsqb : osumsqa;
    int Rows = isB2 ? Rowsb : Rowsa;
    int bx   = isB2 ? (int)blockIdx.x - gxa : (int)blockIdx.x;
    float et = 1.0f + *(isB2 ? epsb : epsa);
    kres_body(A0, A1, et, Bt, C, Rows, osum, osumsq, bx, smem);
}

// ---------------- two same-shape MODE3 problems in one grid ----------------
template <int MODE, int K>
__global__ __launch_bounds__(256, 2)
void k_gemm_pair(const float* A0a, const float* A1a, const float* scla, const float* shfa,
                 const float* epsa, const float* Bta, float* Ca, int Rowsa,
                 float* osuma, float* osumsqa,
                 const float* A0b, const float* A1b, const float* sclb, const float* shfb,
                 const float* epsb, const float* Btb, float* Cb, int Rowsb,
                 float* osumb, float* osumsqb,
                 int gxa, int Ncols)
{
    extern __shared__ float smem[];
    uint32_t sB_u32 = smem_u32(smem + 8192);

    const bool isB = (int)blockIdx.x >= gxa;
    const float* __restrict__ A0  = isB ? A0b  : A0a;
    const float* __restrict__ A1  = isB ? A1b  : A1a;
    const float* __restrict__ scl = isB ? sclb : scla;
    const float* __restrict__ shf = isB ? shfb : shfa;
    const float* __restrict__ Bt  = isB ? Btb  : Bta;
    float* __restrict__ C         = isB ? Cb   : Ca;
    float* __restrict__ osum      = isB ? osumb : osuma;
    float* __restrict__ osumsq    = isB ? osumsqb : osumsqa;
    int Rows = isB ? Rowsb : Rowsa;
    int bx   = isB ? (int)blockIdx.x - gxa : (int)blockIdx.x;

    float et = 1.0f;
    if (MODE == 2) et = 1.0f + *(isB ? epsb : epsa);

    gemm_body<MODE, K>(A0, A1, scl, shf, et, Bt, C, Rows, Ncols, osum, osumsq,
                       bx, blockIdx.y, smem, sB_u32);
}

// ---------------- BN scale/shift from sums (single) ----------------
__global__ void k_finalize(int C, float invR,
                           const float* __restrict__ g, const float* __restrict__ b,
                           const float* __restrict__ sum, const float* __restrict__ sumsq,
                           float* __restrict__ scale, float* __restrict__ shift)
{
    int c = threadIdx.x;
    if (c < C) {
        float m   = sum[c] * invR;
        float var = sumsq[c] * invR - m * m;
        float s   = g[c] * rsqrtf(var + BN_EPS);
        scale[c] = s;
        shift[c] = b[c] - m * s;
    }
}

// ---------------- BN scale/shift for two norms in one launch (512 threads) ----------------
__global__ void k_finalize2(int C1, float invR1, const float* __restrict__ g1,
                            const float* __restrict__ b1, const float* __restrict__ sum1,
                            const float* __restrict__ sumsq1, float* __restrict__ scale1,
                            float* __restrict__ shift1,
                            int C2, float invR2, const float* __restrict__ g2,
                            const float* __restrict__ b2, const float* __restrict__ sum2,
                            const float* __restrict__ sumsq2, float* __restrict__ scale2,
                            float* __restrict__ shift2)
{
    int t = threadIdx.x;
    if (t < 256) {
        if (t < C1) {
            float m   = sum1[t] * invR1;
            float var = sumsq1[t] * invR1 - m * m;
            float s   = g1[t] * rsqrtf(var + BN_EPS);
            scale1[t] = s;
            shift1[t] = b1[t] - m * s;
        }
    } else {
        int c = t - 256;
        if (c < C2) {
            float m   = sum2[c] * invR2;
            float var = sumsq2[c] * invR2 - m * m;
            float s   = g2[c] * rsqrtf(var + BN_EPS);
            scale2[c] = s;
            shift2[c] = b2[c] - m * s;
        }
    }
}

// ---------------- in-place BN affine + ReLU for two tensors ----------------
__global__ void k_apply2(float* __restrict__ X1, long long n4_1,
                         const float* __restrict__ scale1, const float* __restrict__ shift1,
                         float* __restrict__ X2, long long n4_2,
                         const float* __restrict__ scale2, const float* __restrict__ shift2)
{
    long long total = n4_1 + n4_2;
    for (long long idx = blockIdx.x * (long long)blockDim.x + threadIdx.x; idx < total;
         idx += (long long)gridDim.x * blockDim.x) {
        float* X; const float *scale, *shift; long long i;
        if (idx < n4_1) { X = X1; scale = scale1; shift = shift1; i = idx; }
        else            { X = X2; scale = scale2; shift = shift2; i = idx - n4_1; }
        int c4 = (int)(i & 31);
        float4 v  = ((float4*)X)[i];
        float4 sc = *(const float4*)(scale + c4 * 4);
        float4 sh = *(const float4*)(shift + c4 * 4);
        v.x = fmaxf(fmaf(v.x, sc.x, sh.x), 0.f);
        v.y = fmaxf(fmaf(v.y, sc.y, sh.y), 0.f);
        v.z = fmaxf(fmaf(v.z, sc.z, sh.z), 0.f);
        v.w = fmaxf(fmaf(v.w, sc.w, sh.w), 0.f);
        ((float4*)X)[i] = v;
    }
}

// ---------------- launch ----------------
extern "C" void kernel_launch(void* const* d_in, const int* in_sizes, int n_in,
                              void* d_out, int out_size)
{
    const float* node_rep = (const float*)d_in[0];
    const float* edge_rep = (const float*)d_in[1];
    const int*   n2e      = (const int*)  d_in[2];
    const int*   src = n2e;
    const int*   dst = n2e + MM;
    const float* Wa  = (const float*)d_in[3];
    const float* ga  = (const float*)d_in[4];
    const float* ba  = (const float*)d_in[5];
    const float* Wb1 = (const float*)d_in[6];
    const float* gb1 = (const float*)d_in[7];
    const float* bb1 = (const float*)d_in[8];
    const float* Wb2 = (const float*)d_in[9];
    const float* gb2 = (const float*)d_in[10];
    const float* bb2 = (const float*)d_in[11];
    const float* Wl1 = (const float*)d_in[12];
    const float* gl1 = (const float*)d_in[13];
    const float* bl1 = (const float*)d_in[14];
    const float* Wl2 = (const float*)d_in[15];
    const float* gl2 = (const float*)d_in[16];
    const float* bl2 = (const float*)d_in[17];
    const float* eps1 = (const float*)d_in[18];
    const float* eps2 = (const float*)d_in[19];

    float* out_node = (float*)d_out;
    float* out_edge = out_node + (size_t)NN * HH;

    float *p_lift, *p_y1, *p_lvl, *p_yb1, *p_yl1, *p_wt;
    float *p_sum, *p_sumsq, *p_scale, *p_shift;
    cudaGetSymbolAddress((void**)&p_lift,  g_lift);
    cudaGetSymbolAddress((void**)&p_y1,    g_y1);
    cudaGetSymbolAddress((void**)&p_lvl,   g_lvl);
    cudaGetSymbolAddress((void**)&p_yb1,   g_yb1);
    cudaGetSymbolAddress((void**)&p_yl1,   g_yl1);
    cudaGetSymbolAddress((void**)&p_wt,    g_wt);
    cudaGetSymbolAddress((void**)&p_sum,   g_sum);
    cudaGetSymbolAddress((void**)&p_sumsq, g_sumsq);
    cudaGetSymbolAddress((void**)&p_scale, g_scale);
    cudaGetSymbolAddress((void**)&p_shift, g_shift);

    const int SMEM  = 16384 * 4;   // 64 KB
    const int SMEMK = 98304;       // 96 KB
    cudaFuncSetAttribute(k_fused2,            cudaFuncAttributeMaxDynamicSharedMemorySize, SMEMK);
    cudaFuncSetAttribute(k_gemm_pair_kres,    cudaFuncAttributeMaxDynamicSharedMemorySize, SMEMK);
    cudaFuncSetAttribute(k_gemm_pair<3, 256>, cudaFuncAttributeMaxDynamicSharedMemorySize, SMEM);

    // 0) prep
    k_prep<<<2048, 256>>>(Wa, Wb1, Wb2, Wl1, Wl2, p_wt, p_lift, p_lvl, p_sum);

    const int scatter_blocks = (MM * 32 + 255) / 256;
    const int gridE = (EE + 127) / 128;   // 3125
    const int gridN = (NN + 127) / 128;   // 391

    // 1) lift_aggr[dst] += node_rep[src]
    k_scatter<<<scatter_blocks, 256>>>(node_rep, src, dst, p_lift);

    // 2) fused: y1 = [lift|edge]@Wa  AND  yl1 = ((1+eps2)edge+lift)@Wl1  (L2-paired)
    k_fused2<<<dim3(2 * gridE, 1), 256, SMEMK>>>(
        p_lift, edge_rep, p_wt + 0 * 32768, p_wt + 3 * 32768, eps2,
        p_y1, p_yl1, p_sum + 0, p_sumsq + 0, p_sum + 768, p_sumsq + 768);
    k_finalize2<<<1, 512>>>(128, 1.f / EE, ga, ba, p_sum + 0, p_sumsq + 0,
                            p_scale + 0, p_shift + 0,
                            256, 1.f / EE, gl1, bl1, p_sum + 768, p_sumsq + 768,
                            p_scale + 768, p_shift + 768);

    // 3) lvl_aggr[src] += relu(bn(y1))[dst]
    k_scatter_bn<<<scatter_blocks, 256>>>(p_y1, dst, src, p_scale + 0, p_shift + 0, p_lvl);

    // 4) node GEMM4 (A-resident): yb1 = ((1+eps1)node + lvl) @ Wb1
    k_gemm_pair_kres<<<dim3(gridN, 1), 256, SMEMK>>>(
        node_rep, p_lvl, eps1, p_wt + 1 * 32768,
        p_yb1, NN, p_sum + 256, p_sumsq + 256,
        node_rep, p_lvl, eps1, p_wt + 1 * 32768,
        p_yb1, NN, p_sum + 256, p_sumsq + 256,
        gridN);
    k_finalize<<<1, 256>>>(256, 1.f / NN, gb1, bb1, p_sum + 256, p_sumsq + 256,
                           p_scale + 256, p_shift + 256);

    // 5) merged GEMM5: edge (->out_edge) + node (->out_node), both MODE3 K=256 NC=128
    k_gemm_pair<3, 256><<<dim3(gridE + gridN, 1), 256, SMEM>>>(
        p_yl1, nullptr, p_scale + 768, p_shift + 768, nullptr, p_wt + 4 * 32768,
        out_edge, EE, p_sum + 1024, p_sumsq + 1024,
        p_yb1, nullptr, p_scale + 256, p_shift + 256, nullptr, p_wt + 2 * 32768,
        out_node, NN, p_sum + 512, p_sumsq + 512,
        gridE, 128);
    k_finalize2<<<1, 512>>>(128, 1.f / EE, gl2, bl2, p_sum + 1024, p_sumsq + 1024,
                            p_scale + 1024, p_shift + 1024,
                            128, 1.f / NN, gb2, bb2, p_sum + 512, p_sumsq + 512,
                            p_scale + 512, p_shift + 512);

    // 6) merged final BN-ReLU apply on both outputs
    k_apply2<<<2048, 256>>>(out_edge, (long long)EE * HH / 4, p_scale + 1024, p_shift + 1024,
                            out_node, (long long)NN * HH / 4, p_scale + 512, p_shift + 512);
}